// round 7
// baseline (speedup 1.0000x reference)
#include <cuda_runtime.h>
#include <cfloat>

// N=8192 tokens, K=4096, D=1024.
//   idx[n] = argmax_k x[n,k]  (first-occurrence tie-break)
//   out[n,d] = W[d, idx[n]]
//
// K1: per-token argmax -> g_idx (streams x at DRAM roofline).
// K2: inverted gather — 64 k-tiles x 8 d-tiles; each block loads its W tile
//     coalesced (W read exactly once), scans g_idx for matching tokens, and
//     writes their out[n, d0:d0+128] slices (512B contiguous per token-warp).
// No transpose, no Wt intermediate, no global atomics, no reset state.

#define NTOK 8192
#define KDIM 4096
#define DDIM 1024

__device__ int g_idx[NTOK];

// ---------------- K1: argmax only ----------------
__global__ void __launch_bounds__(256) argmax_kernel(const float* __restrict__ x)
{
    const int n   = blockIdx.x;
    const int tid = threadIdx.x;

    const float4* xr = reinterpret_cast<const float4*>(x + (size_t)n * KDIM);
    float best = -FLT_MAX;
    int   bi   = 0x7fffffff;

    #pragma unroll
    for (int it = 0; it < (KDIM / 4) / 256; ++it) {
        int c = tid + it * 256;
        float4 v = __ldcs(xr + c);
        int base = c * 4;
        if (v.x > best) { best = v.x; bi = base + 0; }
        if (v.y > best) { best = v.y; bi = base + 1; }
        if (v.z > best) { best = v.z; bi = base + 2; }
        if (v.w > best) { best = v.w; bi = base + 3; }
    }

    #pragma unroll
    for (int off = 16; off > 0; off >>= 1) {
        float ov = __shfl_down_sync(0xffffffffu, best, off);
        int   oi = __shfl_down_sync(0xffffffffu, bi,   off);
        if (ov > best || (ov == best && oi < bi)) { best = ov; bi = oi; }
    }

    __shared__ float s_val[8];
    __shared__ int   s_idx[8];
    int warp = tid >> 5;
    int lane = tid & 31;
    if (lane == 0) { s_val[warp] = best; s_idx[warp] = bi; }
    __syncthreads();
    if (warp == 0) {
        best = (lane < 8) ? s_val[lane] : -FLT_MAX;
        bi   = (lane < 8) ? s_idx[lane] : 0x7fffffff;
        #pragma unroll
        for (int off = 4; off > 0; off >>= 1) {
            float ov = __shfl_down_sync(0xffffffffu, best, off);
            int   oi = __shfl_down_sync(0xffffffffu, bi,   off);
            if (ov > best || (ov == best && oi < bi)) { best = ov; bi = oi; }
        }
        if (lane == 0) g_idx[n] = bi;
    }
}

// ---------------- K2: inverted tiled gather ----------------
#define KT 64            // k-columns per tile
#define DT 128           // d-rows per tile
#define NKT (KDIM / KT)  // 64 k-tiles
#define NDT (DDIM / DT)  // 8  d-tiles
#define CHUNK 2048       // tokens scanned per pass

__global__ void __launch_bounds__(256) scatter_gather_kernel(
    const float* __restrict__ W, float* __restrict__ out)
{
    __shared__ float sw[DT][KT + 1];   // W tile, [d][k], pad to dodge conflicts
    __shared__ int   s_tok[CHUNK];
    __shared__ int   s_cnt;

    const int tid = threadIdx.x;
    const int kt  = blockIdx.x >> 3;         // 0..63
    const int dt  = blockIdx.x & 7;          // 0..7
    const int k0  = kt * KT;
    const int d0  = dt * DT;

    // ---- load W tile coalesced: rows along d, 64 floats along k per row ----
    {
        const int tx = tid & 15;             // float4 lane within row
        const int r0 = tid >> 4;             // 0..15
        #pragma unroll
        for (int p = 0; p < DT / 16; ++p) {  // 8 passes
            int r = r0 + 16 * p;
            float4 v = __ldcs(reinterpret_cast<const float4*>(
                W + (size_t)(d0 + r) * KDIM + (k0 + 4 * tx)));
            sw[r][4 * tx + 0] = v.x;
            sw[r][4 * tx + 1] = v.y;
            sw[r][4 * tx + 2] = v.z;
            sw[r][4 * tx + 3] = v.w;
        }
    }
    __syncthreads();

    const int lane = tid & 31;
    const int warp = tid >> 5;

    // ---- scan tokens in chunks; emit out rows for matches ----
    for (int c0 = 0; c0 < NTOK; c0 += CHUNK) {
        if (tid == 0) s_cnt = 0;
        __syncthreads();

        #pragma unroll
        for (int j = 0; j < CHUNK / 256; ++j) {
            int i = c0 + tid + j * 256;
            int v = g_idx[i];
            if ((v >> 6) == kt) {
                int s = atomicAdd(&s_cnt, 1);
                s_tok[s] = i | ((v & (KT - 1)) << 16);
            }
        }
        __syncthreads();

        const int cnt = s_cnt;
        for (int w = warp; w < cnt; w += 8) {
            int e = s_tok[w];
            int n = e & 0xFFFF;
            int c = e >> 16;
            float4 o;
            o.x = sw[4 * lane + 0][c];
            o.y = sw[4 * lane + 1][c];
            o.z = sw[4 * lane + 2][c];
            o.w = sw[4 * lane + 3][c];
            __stcs(reinterpret_cast<float4*>(out + (size_t)n * DDIM + d0) + lane, o);
        }
        __syncthreads();
    }
}

extern "C" void kernel_launch(void* const* d_in, const int* in_sizes, int n_in,
                              void* d_out, int out_size) {
    const float* x = (const float*)d_in[0];   // [N, K]
    const float* W = (const float*)d_in[1];   // [D, K]
    float* out = (float*)d_out;               // [N, D]

    argmax_kernel<<<NTOK, 256>>>(x);
    scatter_gather_kernel<<<NKT * NDT, 256>>>(W, out);
}

// round 8
// speedup vs baseline: 1.3078x; 1.3078x over previous
#include <cuda_runtime.h>
#include <cfloat>

// N=8192 tokens, K=4096, D=1024.
//   idx[n] = argmax_k x[n,k]  (first-occurrence tie-break)
//   out[n,d] = W[d, idx[n]]
//
// K1: float4 transpose W [D,K] -> g_Wt [K,D]. Triggers programmatic launch
//     completion at entry so K2 may start while K1 runs.
// K2: fused per-token argmax + row gather (R5's 74%-DRAM kernel), launched
//     with PDL. The argmax phase (x-only) overlaps K1; before reading g_Wt
//     it calls cudaGridDependencySynchronize() (waits for K1 done+flush).

#define NTOK 8192
#define KDIM 4096
#define DDIM 1024
#define TP_TILE 64
#define TP_BLOCKS ((KDIM / TP_TILE) * (DDIM / TP_TILE))   // 1024

__device__ float g_Wt[(size_t)KDIM * DDIM];   // 16 MB scratch

// ---------------- K1: transpose, float4 both sides ----------------
__global__ void __launch_bounds__(256) transpose_kernel(const float* __restrict__ W)
{
#if __CUDA_ARCH__ >= 900
    cudaTriggerProgrammaticLaunchCompletion();   // let K2 launch & overlap
#endif
    __shared__ float t[TP_TILE][TP_TILE + 1];
    const int bid = blockIdx.x;
    const int tid = threadIdx.x;
    const int k0 = (bid % (KDIM / TP_TILE)) * TP_TILE;
    const int d0 = (bid / (KDIM / TP_TILE)) * TP_TILE;
    const int tx = tid & 15;     // float4 lane along fast dim
    const int ty = tid >> 4;     // row 0..15

    #pragma unroll
    for (int i = 0; i < 4; ++i) {
        int r = ty + 16 * i;
        float4 v = __ldcs(reinterpret_cast<const float4*>(
            W + (size_t)(d0 + r) * KDIM + (k0 + 4 * tx)));
        t[r][4 * tx + 0] = v.x;
        t[r][4 * tx + 1] = v.y;
        t[r][4 * tx + 2] = v.z;
        t[r][4 * tx + 3] = v.w;
    }
    __syncthreads();

    #pragma unroll
    for (int i = 0; i < 4; ++i) {
        int r = ty + 16 * i;
        float4 v;
        v.x = t[4 * tx + 0][r];
        v.y = t[4 * tx + 1][r];
        v.z = t[4 * tx + 2][r];
        v.w = t[4 * tx + 3][r];
        *reinterpret_cast<float4*>(
            g_Wt + (size_t)(k0 + r) * DDIM + (d0 + 4 * tx)) = v;
    }
}

// ---------------- K2: fused argmax + row gather (PDL consumer) ----------------
__global__ void __launch_bounds__(256) argmax_gather_kernel(
    const float* __restrict__ x, float* __restrict__ out)
{
    const int n   = blockIdx.x;
    const int tid = threadIdx.x;

    // ---- argmax phase: only reads x, overlaps K1 ----
    const float4* xr = reinterpret_cast<const float4*>(x + (size_t)n * KDIM);
    float best = -FLT_MAX;
    int   bi   = 0x7fffffff;

    #pragma unroll
    for (int it = 0; it < (KDIM / 4) / 256; ++it) {
        int c = tid + it * 256;
        float4 v = __ldcs(xr + c);
        int base = c * 4;
        if (v.x > best) { best = v.x; bi = base + 0; }
        if (v.y > best) { best = v.y; bi = base + 1; }
        if (v.z > best) { best = v.z; bi = base + 2; }
        if (v.w > best) { best = v.w; bi = base + 3; }
    }

    // warp reduce (smaller index wins ties)
    #pragma unroll
    for (int off = 16; off > 0; off >>= 1) {
        float ov = __shfl_down_sync(0xffffffffu, best, off);
        int   oi = __shfl_down_sync(0xffffffffu, bi,   off);
        if (ov > best || (ov == best && oi < bi)) { best = ov; bi = oi; }
    }

    // block reduce across 8 warps
    __shared__ float s_val[8];
    __shared__ int   s_idx[8];
    __shared__ int   s_final;
    int warp = tid >> 5;
    int lane = tid & 31;
    if (lane == 0) { s_val[warp] = best; s_idx[warp] = bi; }
    __syncthreads();
    if (warp == 0) {
        best = (lane < 8) ? s_val[lane] : -FLT_MAX;
        bi   = (lane < 8) ? s_idx[lane] : 0x7fffffff;
        #pragma unroll
        for (int off = 4; off > 0; off >>= 1) {
            float ov = __shfl_down_sync(0xffffffffu, best, off);
            int   oi = __shfl_down_sync(0xffffffffu, bi,   off);
            if (ov > best || (ov == best && oi < bi)) { best = ov; bi = oi; }
        }
        if (lane == 0) s_final = bi;
    }
    __syncthreads();
    const int idx = s_final;

    // ---- wait for K1 (transpose) completion + memory flush ----
#if __CUDA_ARCH__ >= 900
    cudaGridDependencySynchronize();
#endif

    // ---- coalesced row copy: out[n,:] = g_Wt[idx,:] ----
    const float4* src = reinterpret_cast<const float4*>(g_Wt + (size_t)idx * DDIM);
    float4*       dst = reinterpret_cast<float4*>(out + (size_t)n * DDIM);
    __stcs(dst + tid, src[tid]);
}

extern "C" void kernel_launch(void* const* d_in, const int* in_sizes, int n_in,
                              void* d_out, int out_size) {
    const float* x = (const float*)d_in[0];   // [N, K]
    const float* W = (const float*)d_in[1];   // [D, K]
    float* out = (float*)d_out;               // [N, D]

    transpose_kernel<<<TP_BLOCKS, 256>>>(W);

    // K2 with programmatic dependent launch: may start while K1 runs;
    // in-kernel cudaGridDependencySynchronize() provides the data dependency.
    cudaLaunchConfig_t cfg = {};
    cfg.gridDim  = dim3(NTOK, 1, 1);
    cfg.blockDim = dim3(256, 1, 1);
    cfg.dynamicSmemBytes = 0;
    cfg.stream = 0;
    cudaLaunchAttribute attr[1];
    attr[0].id = cudaLaunchAttributeProgrammaticStreamSerialization;
    attr[0].val.programmaticStreamSerializationAllowed = 1;
    cfg.attrs = attr;
    cfg.numAttrs = 1;
    cudaLaunchKernelEx(&cfg, argmax_gather_kernel, x, out);
}